// round 8
// baseline (speedup 1.0000x reference)
#include <cuda_runtime.h>
#include <cuda_fp16.h>
#include <cuda_bf16.h>
#include <cstdint>

#define Bq 8
#define Nq 1024
#define Dq 256
#define Hq 8
#define Uq 64
#define HU 512

// -------- scratch (device globals; no allocation in kernel_launch) --------
__device__ __half g_feat16[Bq * Nq * HU];     // features (fp16)
__device__ __half g_fres16[Bq * Nq * HU];     // residual features (fp16)
__device__ float  g_as[Bq * Nq * Hq];
__device__ float  g_an[Bq * Nq * Hq];
__device__ float  g_cm[Bq * Hq];              // colmax of an per (b,h)
__device__ __nv_bfloat16 gWb[768 * 1024];     // stacked split-bf16 weights

// ------------------------- helpers ---------------------------------------
__device__ __forceinline__ uint32_t smem_u32(const void* p) {
    uint32_t a;
    asm("{ .reg .u64 t; cvta.to.shared.u64 t, %1; cvt.u32.u64 %0, t; }" : "=r"(a) : "l"(p));
    return a;
}
__device__ __forceinline__ uint32_t pkb2(__nv_bfloat16 a, __nv_bfloat16 b) {
    __nv_bfloat162 p = __halves2bfloat162(a, b);
    return *reinterpret_cast<uint32_t*>(&p);
}
__device__ __forceinline__ void ldsm_x4(uint32_t addr, uint32_t& r0, uint32_t& r1,
                                        uint32_t& r2, uint32_t& r3) {
    asm volatile("ldmatrix.sync.aligned.m8n8.x4.shared.b16 {%0,%1,%2,%3}, [%4];"
                 : "=r"(r0), "=r"(r1), "=r"(r2), "=r"(r3) : "r"(addr));
}
__device__ __forceinline__ void ldsm_x2t(uint32_t addr, uint32_t& r0, uint32_t& r1) {
    asm volatile("ldmatrix.sync.aligned.m8n8.x2.trans.shared.b16 {%0,%1}, [%2];"
                 : "=r"(r0), "=r"(r1) : "r"(addr));
}
__device__ __forceinline__ void mma16816_bf(float* d, uint32_t a0, uint32_t a1,
                                            uint32_t a2, uint32_t a3,
                                            uint32_t b0, uint32_t b1) {
    asm volatile(
        "mma.sync.aligned.m16n8k16.row.col.f32.bf16.bf16.f32 "
        "{%0,%1,%2,%3}, {%4,%5,%6,%7}, {%8,%9}, {%0,%1,%2,%3};"
        : "+f"(d[0]), "+f"(d[1]), "+f"(d[2]), "+f"(d[3])
        : "r"(a0), "r"(a1), "r"(a2), "r"(a3), "r"(b0), "r"(b1));
}
__device__ __forceinline__ void mma16816_hf(float* d, uint32_t a0, uint32_t a1,
                                            uint32_t a2, uint32_t a3,
                                            uint32_t b0, uint32_t b1) {
    asm volatile(
        "mma.sync.aligned.m16n8k16.row.col.f32.f16.f16.f32 "
        "{%0,%1,%2,%3}, {%4,%5,%6,%7}, {%8,%9}, {%0,%1,%2,%3};"
        : "+f"(d[0]), "+f"(d[1]), "+f"(d[2]), "+f"(d[3])
        : "r"(a0), "r"(a1), "r"(a2), "r"(a3), "r"(b0), "r"(b1));
}
__device__ __forceinline__ float ex2f(float x) {
    float r;
    asm("ex2.approx.f32 %0, %1;" : "=f"(r) : "f"(x));
    return r;
}
#define L2E 1.4426950408889634f

// ------------- Kernel 0: W -> stacked bf16 [768][1024] -------------------
__global__ __launch_bounds__(256) void wconv_k(const float* __restrict__ Wk,
                                               const float* __restrict__ Wr) {
    int idx = blockIdx.x * 256 + threadIdx.x;
    int kv = idx >> 10;
    int nc = idx & 1023;
    int part = kv >> 8;
    int k = kv & 255;
    const float* W = (nc >> 9) ? Wr : Wk;
    float x = W[(size_t)k * HU + (nc & 511)];
    __nv_bfloat16 hb = __float2bfloat16_rn(x);
    __nv_bfloat16 o = (part == 2) ? __float2bfloat16_rn(x - __bfloat162float(hb)) : hb;
    gWb[idx] = o;
}

// --- Kernel 1: mma.sync split-bf16 GEMM + logits + fp16 writes -----------
#define ASTRIDE 72
#define BSTRIDE 136
__global__ __launch_bounds__(256) void gemm_mma_k(const float* __restrict__ Xg,
                                                  const float* __restrict__ aks,
                                                  const float* __restrict__ akn) {
    __shared__ __nv_bfloat16 As[128 * ASTRIDE];
    __shared__ __nv_bfloat16 Bs[64 * BSTRIDE];
    __shared__ float s_part[4][128][2];
    __shared__ float s_ak[128], s_an[128];

    const int tid = threadIdx.x;
    const int l   = tid & 31;
    const int wid = tid >> 5;
    const int wm  = wid & 1;
    const int wn  = wid >> 1;
    const int bx  = blockIdx.x;
    const int by  = blockIdx.y;

    const uint32_t aBase = smem_u32(As);
    const uint32_t bBase = smem_u32(Bs);

    float acc[4][4][4];
#pragma unroll
    for (int i = 0; i < 4; i++)
#pragma unroll
        for (int j = 0; j < 4; j++)
#pragma unroll
            for (int r = 0; r < 4; r++) acc[i][j][r] = 0.0f;

    for (int ic = 0; ic < 12; ic++) {
        const int part = ic >> 2;
        const int k0 = (ic & 3) * 64;
#pragma unroll
        for (int i = 0; i < 8; i++) {
            int slot = i * 256 + tid;
            int row = slot >> 4;
            int c4 = slot & 15;
            float4 v = *(const float4*)&Xg[(size_t)(by * 128 + row) * Dq + k0 + c4 * 4];
            __nv_bfloat16 o0, o1, o2, o3;
            __nv_bfloat16 h0 = __float2bfloat16_rn(v.x);
            __nv_bfloat16 h1 = __float2bfloat16_rn(v.y);
            __nv_bfloat16 h2 = __float2bfloat16_rn(v.z);
            __nv_bfloat16 h3 = __float2bfloat16_rn(v.w);
            if (part == 1) {
                o0 = __float2bfloat16_rn(v.x - __bfloat162float(h0));
                o1 = __float2bfloat16_rn(v.y - __bfloat162float(h1));
                o2 = __float2bfloat16_rn(v.z - __bfloat162float(h2));
                o3 = __float2bfloat16_rn(v.w - __bfloat162float(h3));
            } else {
                o0 = h0; o1 = h1; o2 = h2; o3 = h3;
            }
            *(uint2*)&As[row * ASTRIDE + c4 * 4] = make_uint2(pkb2(o0, o1), pkb2(o2, o3));
        }
#pragma unroll
        for (int i = 0; i < 4; i++) {
            int slot = i * 256 + tid;
            int r = slot >> 4;
            int c8 = slot & 15;
            uint4 v = *(const uint4*)&gWb[(size_t)(ic * 64 + r) * 1024 + bx * 128 + c8 * 8];
            *(uint4*)&Bs[r * BSTRIDE + c8 * 8] = v;
        }
        __syncthreads();
#pragma unroll
        for (int kk = 0; kk < 4; kk++) {
            uint32_t a[4][4], b[4][2];
#pragma unroll
            for (int mf = 0; mf < 4; mf++) {
                int row = wm * 64 + mf * 16 + (l & 15);
                int col = kk * 16 + (l >> 4) * 8;
                ldsm_x4(aBase + (row * ASTRIDE + col) * 2,
                        a[mf][0], a[mf][1], a[mf][2], a[mf][3]);
            }
#pragma unroll
            for (int nf = 0; nf < 4; nf++) {
                int lr = l & 15;
                int row = kk * 16 + (lr & 7) + (lr >> 3) * 8;
                int col = wn * 32 + nf * 8;
                ldsm_x2t(bBase + (row * BSTRIDE + col) * 2, b[nf][0], b[nf][1]);
            }
#pragma unroll
            for (int mf = 0; mf < 4; mf++)
#pragma unroll
                for (int nf = 0; nf < 4; nf++)
                    mma16816_bf(acc[mf][nf], a[mf][0], a[mf][1], a[mf][2], a[mf][3],
                                b[nf][0], b[nf][1]);
        }
        __syncthreads();
    }

    if (bx < 4 && tid < 128) {
        s_ak[tid] = aks[bx * 128 + tid];
        s_an[tid] = akn[bx * 128 + tid];
    }
    __syncthreads();

#pragma unroll
    for (int mf = 0; mf < 4; mf++) {
        int r_lo = wm * 64 + mf * 16 + (l >> 2);
        int m_lo = by * 128 + r_lo;
        int m_hi = m_lo + 8;
        float sSl = 0.f, sSh = 0.f, sNl = 0.f, sNh = 0.f;
#pragma unroll
        for (int nf = 0; nf < 4; nf++) {
            int col_l = wn * 32 + nf * 8 + (l & 3) * 2;
            float c0 = acc[mf][nf][0], c1 = acc[mf][nf][1];
            float c2 = acc[mf][nf][2], c3 = acc[mf][nf][3];
            if (bx < 4) {
                int col = bx * 128 + col_l;
                *(__half2*)&g_feat16[(size_t)m_lo * HU + col] = __floats2half2_rn(c0, c1);
                *(__half2*)&g_feat16[(size_t)m_hi * HU + col] = __floats2half2_rn(c2, c3);
                sSl += c0 * s_ak[col_l] + c1 * s_ak[col_l + 1];
                sSh += c2 * s_ak[col_l] + c3 * s_ak[col_l + 1];
                sNl += c0 * s_an[col_l] + c1 * s_an[col_l + 1];
                sNh += c2 * s_an[col_l] + c3 * s_an[col_l + 1];
            } else {
                int col = (bx - 4) * 128 + col_l;
                *(__half2*)&g_fres16[(size_t)m_lo * HU + col] = __floats2half2_rn(c0, c1);
                *(__half2*)&g_fres16[(size_t)m_hi * HU + col] = __floats2half2_rn(c2, c3);
            }
        }
        if (bx < 4) {
#pragma unroll
            for (int o = 1; o <= 2; o <<= 1) {
                sSl += __shfl_xor_sync(0xffffffffu, sSl, o);
                sSh += __shfl_xor_sync(0xffffffffu, sSh, o);
                sNl += __shfl_xor_sync(0xffffffffu, sNl, o);
                sNh += __shfl_xor_sync(0xffffffffu, sNh, o);
            }
            if ((l & 3) == 0) {
                s_part[wn][r_lo][0] = sSl;
                s_part[wn][r_lo][1] = sNl;
                s_part[wn][r_lo + 8][0] = sSh;
                s_part[wn][r_lo + 8][1] = sNh;
            }
        }
    }
    __syncthreads();
    if (bx < 4) {
        int row = tid >> 1;
        int sn = tid & 1;
        float v0 = s_part[0][row][sn] + s_part[1][row][sn];
        float v1 = s_part[2][row][sn] + s_part[3][row][sn];
        int m = by * 128 + row;
        float* dst = sn ? g_an : g_as;
        dst[(size_t)m * Hq + bx * 2] = v0;
        dst[(size_t)m * Hq + bx * 2 + 1] = v1;
    }
}

// --------- Kernel 2: colmax of an per (b,h) -------------------------------
__global__ __launch_bounds__(128) void colmax_k() {
    int b = blockIdx.x >> 3, h = blockIdx.x & 7;
    int t = threadIdx.x;
    __shared__ float red[128];
    float m = -1e30f;
    for (int k = t; k < Nq; k += 128)
        m = fmaxf(m, g_an[((size_t)(b * Nq + k)) * Hq + h]);
    red[t] = m;
    __syncthreads();
    for (int s = 64; s; s >>= 1) {
        if (t < s) red[t] = fmaxf(red[t], red[t + s]);
        __syncthreads();
    }
    if (t == 0) g_cm[blockIdx.x] = red[0];
}

// --------- Kernel 3: sparse-scatter flash aggregation ---------------------
// grid (hg=2, nt=8, b=8), 256 threads (8 warps). Each block: 4 heads x 128 n-rows.
#define PSTRIDE 136
#define VSTRIDE 72
#define ECAP 2560
#define OFF_P     0
#define OFF_V     34816
#define OFF_E     53248
#define OFF_AN    94208
#define OFF_AS    94720
#define OFF_ML    96768
#define OFF_SUM   98816
#define OFF_BIAS  99328
#define OFF_CNT   100352
#define AGG_SMEM  100416

__global__ __launch_bounds__(256) void agg_k(const float* __restrict__ A,
                                             const float* __restrict__ bias,
                                             float* __restrict__ out) {
    extern __shared__ char sm[];
    __half* sP = (__half*)(sm + OFF_P);
    __half* sV = (__half*)(sm + OFF_V);
    unsigned short* sE = (unsigned short*)(sm + OFF_E);
    float* sAn = (float*)(sm + OFF_AN);
    float* sAs = (float*)(sm + OFF_AS);
    float* sMl = (float*)(sm + OFF_ML);
    float* sSum = (float*)(sm + OFF_SUM);
    float* sBias = (float*)(sm + OFF_BIAS);
    int* sCnt = (int*)(sm + OFF_CNT);

    const int tid = threadIdx.x;
    const int l = tid & 31;
    const int w = tid >> 5;
    const int hg = blockIdx.x;
    const int nt = blockIdx.y;
    const int b  = blockIdx.z;
    const int n0 = nt * 128;

    // ---- phase 0: preloads
    if (tid < 8) sCnt[tid] = 0;
    sBias[tid] = bias[hg * 256 + tid];
    if (tid < 128) {
#pragma unroll
        for (int h4 = 0; h4 < 4; h4++) {
            int h = hg * 4 + h4;
            float as = g_as[((size_t)(b * Nq + n0 + tid)) * Hq + h];
            float x = as + g_cm[b * 8 + h];
            float mr = x > 0.f ? x : 0.2f * x;
            sAs[h4 * 128 + tid] = as;
            sMl[h4 * 128 + tid] = mr * L2E;
        }
    }
    __syncthreads();

    // ---- phase 1: A scan -> per-kt edge lists
    for (int r = w; r < 128; r += 8) {
        const float4* Ar = (const float4*)(A + ((size_t)(b * Nq + n0 + r)) * Nq);
#pragma unroll
        for (int it = 0; it < 8; it++) {
            float4 v = Ar[it * 32 + l];
            unsigned b0 = __ballot_sync(~0u, v.x > 0.f);
            unsigned b1 = __ballot_sync(~0u, v.y > 0.f);
            unsigned b2 = __ballot_sync(~0u, v.z > 0.f);
            unsigned b3 = __ballot_sync(~0u, v.w > 0.f);
            int t0 = __popc(b0), t1 = __popc(b1), t2 = __popc(b2), t3 = __popc(b3);
            int tot = t0 + t1 + t2 + t3;
            int base = 0;
            if (l == 0 && tot) base = atomicAdd(&sCnt[it], tot);
            base = __shfl_sync(~0u, base, 0);
            unsigned lm = (1u << l) - 1u;
            unsigned short* eb = sE + it * ECAP + base;
            int rr = r << 7;
            if (v.x > 0.f) eb[__popc(b0 & lm)] = (unsigned short)(rr | (l * 4 + 0));
            if (v.y > 0.f) eb[t0 + __popc(b1 & lm)] = (unsigned short)(rr | (l * 4 + 1));
            if (v.z > 0.f) eb[t0 + t1 + __popc(b2 & lm)] = (unsigned short)(rr | (l * 4 + 2));
            if (v.w > 0.f) eb[t0 + t1 + t2 + __popc(b3 & lm)] = (unsigned short)(rr | (l * 4 + 3));
        }
    }
    __syncthreads();

    const uint32_t pBase = smem_u32(sP);
    const uint32_t vBase = smem_u32(sV);

    for (int h4 = 0; h4 < 4; h4++) {
        const int h = hg * 4 + h4;
        float acc[8][4];
#pragma unroll
        for (int nf = 0; nf < 8; nf++)
#pragma unroll
            for (int r = 0; r < 4; r++) acc[nf][r] = 0.0f;

        __syncthreads();                     // prev epilogue done reading sSum
        if (tid < 128) sSum[tid] = 0.f;

        for (int kt = 0; kt < 8; kt++) {
            __syncthreads();                 // prev mma done with P/V; sums visible
            if (tid < 128)
                sAn[tid] = g_an[((size_t)(b * Nq + kt * 128 + tid)) * Hq + h];
#pragma unroll
            for (int i = 0; i < 4; i++) {
                int s = i * 256 + tid;
                int row = s >> 3, q = s & 7;
                uint4 v = *(const uint4*)(g_feat16 +
                    ((size_t)(b * Nq + kt * 128 + row)) * HU + h * Uq + q * 8);
                *(uint4*)&sV[row * VSTRIDE + q * 8] = v;
            }
            uint4 z = make_uint4(0, 0, 0, 0);
#pragma unroll
            for (int i = 0; i < 9; i++) {
                int s = i * 256 + tid;
                if (s < 2176) ((uint4*)sP)[s] = z;
            }
            __syncthreads();
            // scatter edges
            int ce = sCnt[kt];
            for (int e = tid; e < ce; e += 256) {
                int pk = sE[kt * ECAP + e];
                int r = pk >> 7, kl = pk & 127;
                float x = sAs[h4 * 128 + r] + sAn[kl];
                float y = x > 0.f ? x : 0.2f * x;
                float wv = ex2f(fmaf(y, L2E, -sMl[h4 * 128 + r]));
                sP[r * PSTRIDE + kl] = __float2half_rn(wv);
                atomicAdd(&sSum[r], wv);
            }
            __syncthreads();
            // mma: acc += P[w*16..+16, :] x V[:, 0..63]
#pragma unroll
            for (int kk = 0; kk < 8; kk++) {
                uint32_t a0, a1, a2, a3;
                int arow = w * 16 + (l & 15);
                int acol = kk * 16 + (l >> 4) * 8;
                ldsm_x4(pBase + (arow * PSTRIDE + acol) * 2, a0, a1, a2, a3);
#pragma unroll
                for (int nf = 0; nf < 8; nf++) {
                    uint32_t b0, b1;
                    int lr = l & 15;
                    int brow = kk * 16 + (lr & 7) + (lr >> 3) * 8;
                    ldsm_x2t(vBase + (brow * VSTRIDE + nf * 8) * 2, b0, b1);
                    mma16816_hf(acc[nf], a0, a1, a2, a3, b0, b1);
                }
            }
        }

        // ---- epilogue for this head
        int r1 = w * 16 + (l >> 2);
        int r2 = r1 + 8;
        float i1 = 1.f / sSum[r1];
        float i2 = 1.f / sSum[r2];
#pragma unroll
        for (int nf = 0; nf < 8; nf++) {
            int c = nf * 8 + (l & 3) * 2;
            size_t o1 = ((size_t)(b * Nq + n0 + r1)) * HU + h * Uq + c;
            size_t o2 = ((size_t)(b * Nq + n0 + r2)) * HU + h * Uq + c;
            float2 res1 = __half22float2(*(const __half2*)(g_fres16 + o1));
            float2 res2 = __half22float2(*(const __half2*)(g_fres16 + o2));
            float bx = sBias[h4 * 64 + c], by = sBias[h4 * 64 + c + 1];
            float2 v1, v2;
            v1.x = fmaxf(acc[nf][0] * i1 + res1.x + bx, 0.f);
            v1.y = fmaxf(acc[nf][1] * i1 + res1.y + by, 0.f);
            v2.x = fmaxf(acc[nf][2] * i2 + res2.x + bx, 0.f);
            v2.y = fmaxf(acc[nf][3] * i2 + res2.y + by, 0.f);
            *(float2*)(out + o1) = v1;
            *(float2*)(out + o2) = v2;
        }
    }
}

// -------------------------------- launch ---------------------------------
extern "C" void kernel_launch(void* const* d_in, const int* in_sizes, int n_in,
                              void* d_out, int out_size) {
    const float* X    = (const float*)d_in[0];
    const float* A    = (const float*)d_in[1];
    const float* Wk   = (const float*)d_in[2];
    const float* Wr   = (const float*)d_in[3];
    const float* aks  = (const float*)d_in[4];
    const float* akn  = (const float*)d_in[5];
    const float* bias = (const float*)d_in[6];
    float* out = (float*)d_out;

    static bool attr_set = false;
    if (!attr_set) {
        cudaFuncSetAttribute(agg_k, cudaFuncAttributeMaxDynamicSharedMemorySize, AGG_SMEM);
        attr_set = true;
    }

    wconv_k<<<768 * 1024 / 256, 256>>>(Wk, Wr);
    gemm_mma_k<<<dim3(8, 64), 256>>>(X, aks, akn);
    colmax_k<<<64, 128>>>();
    agg_k<<<dim3(2, 8, 8), 256, AGG_SMEM>>>(A, bias, out);
}

// round 9
// speedup vs baseline: 1.5815x; 1.5815x over previous
#include <cuda_runtime.h>
#include <cuda_fp16.h>
#include <cuda_bf16.h>
#include <cstdint>

#define Bq 8
#define Nq 1024
#define Dq 256
#define Hq 8
#define Uq 64
#define HU 512

// -------- scratch (device globals; no allocation in kernel_launch) --------
__device__ __half g_feat16[Bq * Nq * HU];     // features (fp16)
__device__ __half g_fres16[Bq * Nq * HU];     // residual features (fp16)
__device__ float  g_as[Bq * Nq * Hq];
__device__ float  g_an[Bq * Nq * Hq];
__device__ float  g_cm[Bq * Hq];              // colmax of an per (b,h)
__device__ __nv_bfloat16 gWb[768 * 1024];     // stacked split-bf16 weights
#define ECAP 2560
__device__ unsigned short g_edges[512 * ECAP]; // per (b,nt,kt) edge segments
__device__ int g_ecnt[512];

// ------------------------- helpers ---------------------------------------
__device__ __forceinline__ uint32_t smem_u32(const void* p) {
    uint32_t a;
    asm("{ .reg .u64 t; cvta.to.shared.u64 t, %1; cvt.u32.u64 %0, t; }" : "=r"(a) : "l"(p));
    return a;
}
__device__ __forceinline__ uint32_t pkb2(__nv_bfloat16 a, __nv_bfloat16 b) {
    __nv_bfloat162 p = __halves2bfloat162(a, b);
    return *reinterpret_cast<uint32_t*>(&p);
}
__device__ __forceinline__ void ldsm_x4(uint32_t addr, uint32_t& r0, uint32_t& r1,
                                        uint32_t& r2, uint32_t& r3) {
    asm volatile("ldmatrix.sync.aligned.m8n8.x4.shared.b16 {%0,%1,%2,%3}, [%4];"
                 : "=r"(r0), "=r"(r1), "=r"(r2), "=r"(r3) : "r"(addr));
}
__device__ __forceinline__ void ldsm_x2t(uint32_t addr, uint32_t& r0, uint32_t& r1) {
    asm volatile("ldmatrix.sync.aligned.m8n8.x2.trans.shared.b16 {%0,%1}, [%2];"
                 : "=r"(r0), "=r"(r1) : "r"(addr));
}
__device__ __forceinline__ void mma16816_bf(float* d, uint32_t a0, uint32_t a1,
                                            uint32_t a2, uint32_t a3,
                                            uint32_t b0, uint32_t b1) {
    asm volatile(
        "mma.sync.aligned.m16n8k16.row.col.f32.bf16.bf16.f32 "
        "{%0,%1,%2,%3}, {%4,%5,%6,%7}, {%8,%9}, {%0,%1,%2,%3};"
        : "+f"(d[0]), "+f"(d[1]), "+f"(d[2]), "+f"(d[3])
        : "r"(a0), "r"(a1), "r"(a2), "r"(a3), "r"(b0), "r"(b1));
}
__device__ __forceinline__ void mma16816_hf(float* d, uint32_t a0, uint32_t a1,
                                            uint32_t a2, uint32_t a3,
                                            uint32_t b0, uint32_t b1) {
    asm volatile(
        "mma.sync.aligned.m16n8k16.row.col.f32.f16.f16.f32 "
        "{%0,%1,%2,%3}, {%4,%5,%6,%7}, {%8,%9}, {%0,%1,%2,%3};"
        : "+f"(d[0]), "+f"(d[1]), "+f"(d[2]), "+f"(d[3])
        : "r"(a0), "r"(a1), "r"(a2), "r"(a3), "r"(b0), "r"(b1));
}
__device__ __forceinline__ float ex2f(float x) {
    float r;
    asm("ex2.approx.f32 %0, %1;" : "=f"(r) : "f"(x));
    return r;
}
#define L2E 1.4426950408889634f

// ------------- Kernel 0: W -> stacked bf16 [768][1024] -------------------
__global__ __launch_bounds__(256) void wconv_k(const float* __restrict__ Wk,
                                               const float* __restrict__ Wr) {
    int idx = blockIdx.x * 256 + threadIdx.x;
    int kv = idx >> 10;
    int nc = idx & 1023;
    int part = kv >> 8;
    int k = kv & 255;
    const float* W = (nc >> 9) ? Wr : Wk;
    float x = W[(size_t)k * HU + (nc & 511)];
    __nv_bfloat16 hb = __float2bfloat16_rn(x);
    __nv_bfloat16 o = (part == 2) ? __float2bfloat16_rn(x - __bfloat162float(hb)) : hb;
    gWb[idx] = o;
}

// ------------- Kernel 0b: zero edge counters ------------------------------
__global__ void zero_k() { g_ecnt[threadIdx.x] = 0; }

// ------------- Kernel 0c: edge-list build (CSR-ish segments) --------------
// grid (nt=8, b=8), 512 threads (16 warps, warp = row strided by 16).
__global__ __launch_bounds__(512) void ebuild_k(const float* __restrict__ A) {
    const int nt = blockIdx.x, b = blockIdx.y;
    const int l = threadIdx.x & 31, w = threadIdx.x >> 5;
    for (int r = w; r < 128; r += 16) {
        const float4* Ar = (const float4*)(A + ((size_t)(b * Nq + nt * 128 + r)) * Nq);
#pragma unroll
        for (int kt = 0; kt < 8; kt++) {
            float4 v = Ar[kt * 32 + l];
            unsigned b0 = __ballot_sync(~0u, v.x > 0.f);
            unsigned b1 = __ballot_sync(~0u, v.y > 0.f);
            unsigned b2 = __ballot_sync(~0u, v.z > 0.f);
            unsigned b3 = __ballot_sync(~0u, v.w > 0.f);
            int t0 = __popc(b0), t1 = __popc(b1), t2 = __popc(b2), t3 = __popc(b3);
            int tot = t0 + t1 + t2 + t3;
            int base = 0;
            int seg = ((b * 8 + nt) * 8 + kt);
            if (l == 0 && tot) base = atomicAdd(&g_ecnt[seg], tot);
            base = __shfl_sync(~0u, base, 0);
            unsigned lm = (1u << l) - 1u;
            unsigned short* eb = g_edges + (size_t)seg * ECAP + base;
            int rr = r << 7;
            if (v.x > 0.f) eb[__popc(b0 & lm)] = (unsigned short)(rr | (l * 4 + 0));
            if (v.y > 0.f) eb[t0 + __popc(b1 & lm)] = (unsigned short)(rr | (l * 4 + 1));
            if (v.z > 0.f) eb[t0 + t1 + __popc(b2 & lm)] = (unsigned short)(rr | (l * 4 + 2));
            if (v.w > 0.f) eb[t0 + t1 + t2 + __popc(b3 & lm)] = (unsigned short)(rr | (l * 4 + 3));
        }
    }
}

// --- Kernel 1: mma.sync split-bf16 GEMM + logits + fp16 writes -----------
#define ASTRIDE 72
#define BSTRIDE 136
__global__ __launch_bounds__(256) void gemm_mma_k(const float* __restrict__ Xg,
                                                  const float* __restrict__ aks,
                                                  const float* __restrict__ akn) {
    __shared__ __nv_bfloat16 As[128 * ASTRIDE];
    __shared__ __nv_bfloat16 Bs[64 * BSTRIDE];
    __shared__ float s_part[4][128][2];
    __shared__ float s_ak[128], s_an[128];

    const int tid = threadIdx.x;
    const int l   = tid & 31;
    const int wid = tid >> 5;
    const int wm  = wid & 1;
    const int wn  = wid >> 1;
    const int bx  = blockIdx.x;
    const int by  = blockIdx.y;

    const uint32_t aBase = smem_u32(As);
    const uint32_t bBase = smem_u32(Bs);

    float acc[4][4][4];
#pragma unroll
    for (int i = 0; i < 4; i++)
#pragma unroll
        for (int j = 0; j < 4; j++)
#pragma unroll
            for (int r = 0; r < 4; r++) acc[i][j][r] = 0.0f;

    for (int ic = 0; ic < 12; ic++) {
        const int part = ic >> 2;
        const int k0 = (ic & 3) * 64;
#pragma unroll
        for (int i = 0; i < 8; i++) {
            int slot = i * 256 + tid;
            int row = slot >> 4;
            int c4 = slot & 15;
            float4 v = *(const float4*)&Xg[(size_t)(by * 128 + row) * Dq + k0 + c4 * 4];
            __nv_bfloat16 o0, o1, o2, o3;
            __nv_bfloat16 h0 = __float2bfloat16_rn(v.x);
            __nv_bfloat16 h1 = __float2bfloat16_rn(v.y);
            __nv_bfloat16 h2 = __float2bfloat16_rn(v.z);
            __nv_bfloat16 h3 = __float2bfloat16_rn(v.w);
            if (part == 1) {
                o0 = __float2bfloat16_rn(v.x - __bfloat162float(h0));
                o1 = __float2bfloat16_rn(v.y - __bfloat162float(h1));
                o2 = __float2bfloat16_rn(v.z - __bfloat162float(h2));
                o3 = __float2bfloat16_rn(v.w - __bfloat162float(h3));
            } else {
                o0 = h0; o1 = h1; o2 = h2; o3 = h3;
            }
            *(uint2*)&As[row * ASTRIDE + c4 * 4] = make_uint2(pkb2(o0, o1), pkb2(o2, o3));
        }
#pragma unroll
        for (int i = 0; i < 4; i++) {
            int slot = i * 256 + tid;
            int r = slot >> 4;
            int c8 = slot & 15;
            uint4 v = *(const uint4*)&gWb[(size_t)(ic * 64 + r) * 1024 + bx * 128 + c8 * 8];
            *(uint4*)&Bs[r * BSTRIDE + c8 * 8] = v;
        }
        __syncthreads();
#pragma unroll
        for (int kk = 0; kk < 4; kk++) {
            uint32_t a[4][4], b[4][2];
#pragma unroll
            for (int mf = 0; mf < 4; mf++) {
                int row = wm * 64 + mf * 16 + (l & 15);
                int col = kk * 16 + (l >> 4) * 8;
                ldsm_x4(aBase + (row * ASTRIDE + col) * 2,
                        a[mf][0], a[mf][1], a[mf][2], a[mf][3]);
            }
#pragma unroll
            for (int nf = 0; nf < 4; nf++) {
                int lr = l & 15;
                int row = kk * 16 + (lr & 7) + (lr >> 3) * 8;
                int col = wn * 32 + nf * 8;
                ldsm_x2t(bBase + (row * BSTRIDE + col) * 2, b[nf][0], b[nf][1]);
            }
#pragma unroll
            for (int mf = 0; mf < 4; mf++)
#pragma unroll
                for (int nf = 0; nf < 4; nf++)
                    mma16816_bf(acc[mf][nf], a[mf][0], a[mf][1], a[mf][2], a[mf][3],
                                b[nf][0], b[nf][1]);
        }
        __syncthreads();
    }

    if (bx < 4 && tid < 128) {
        s_ak[tid] = aks[bx * 128 + tid];
        s_an[tid] = akn[bx * 128 + tid];
    }
    __syncthreads();

#pragma unroll
    for (int mf = 0; mf < 4; mf++) {
        int r_lo = wm * 64 + mf * 16 + (l >> 2);
        int m_lo = by * 128 + r_lo;
        int m_hi = m_lo + 8;
        float sSl = 0.f, sSh = 0.f, sNl = 0.f, sNh = 0.f;
#pragma unroll
        for (int nf = 0; nf < 4; nf++) {
            int col_l = wn * 32 + nf * 8 + (l & 3) * 2;
            float c0 = acc[mf][nf][0], c1 = acc[mf][nf][1];
            float c2 = acc[mf][nf][2], c3 = acc[mf][nf][3];
            if (bx < 4) {
                int col = bx * 128 + col_l;
                *(__half2*)&g_feat16[(size_t)m_lo * HU + col] = __floats2half2_rn(c0, c1);
                *(__half2*)&g_feat16[(size_t)m_hi * HU + col] = __floats2half2_rn(c2, c3);
                sSl += c0 * s_ak[col_l] + c1 * s_ak[col_l + 1];
                sSh += c2 * s_ak[col_l] + c3 * s_ak[col_l + 1];
                sNl += c0 * s_an[col_l] + c1 * s_an[col_l + 1];
                sNh += c2 * s_an[col_l] + c3 * s_an[col_l + 1];
            } else {
                int col = (bx - 4) * 128 + col_l;
                *(__half2*)&g_fres16[(size_t)m_lo * HU + col] = __floats2half2_rn(c0, c1);
                *(__half2*)&g_fres16[(size_t)m_hi * HU + col] = __floats2half2_rn(c2, c3);
            }
        }
        if (bx < 4) {
#pragma unroll
            for (int o = 1; o <= 2; o <<= 1) {
                sSl += __shfl_xor_sync(0xffffffffu, sSl, o);
                sSh += __shfl_xor_sync(0xffffffffu, sSh, o);
                sNl += __shfl_xor_sync(0xffffffffu, sNl, o);
                sNh += __shfl_xor_sync(0xffffffffu, sNh, o);
            }
            if ((l & 3) == 0) {
                s_part[wn][r_lo][0] = sSl;
                s_part[wn][r_lo][1] = sNl;
                s_part[wn][r_lo + 8][0] = sSh;
                s_part[wn][r_lo + 8][1] = sNh;
            }
        }
    }
    __syncthreads();
    if (bx < 4) {
        int row = tid >> 1;
        int sn = tid & 1;
        float v0 = s_part[0][row][sn] + s_part[1][row][sn];
        float v1 = s_part[2][row][sn] + s_part[3][row][sn];
        int m = by * 128 + row;
        float* dst = sn ? g_an : g_as;
        dst[(size_t)m * Hq + bx * 2] = v0;
        dst[(size_t)m * Hq + bx * 2 + 1] = v1;
    }
}

// --------- Kernel 2: colmax of an per (b,h) -------------------------------
__global__ __launch_bounds__(128) void colmax_k() {
    int b = blockIdx.x >> 3, h = blockIdx.x & 7;
    int t = threadIdx.x;
    __shared__ float red[128];
    float m = -1e30f;
    for (int k = t; k < Nq; k += 128)
        m = fmaxf(m, g_an[((size_t)(b * Nq + k)) * Hq + h]);
    red[t] = m;
    __syncthreads();
    for (int s = 64; s; s >>= 1) {
        if (t < s) red[t] = fmaxf(red[t], red[t + s]);
        __syncthreads();
    }
    if (t == 0) g_cm[blockIdx.x] = red[0];
}

// --------- Kernel 3: sparse-scatter flash aggregation (1 head / block) ----
// grid (h=8, nt=8, b=8) = 512 blocks, 256 threads (8 warps, 16 rows each).
#define PSTRIDE 136
#define VSTRIDE 72
#define OFF_P     0
#define OFF_V     34816
#define OFF_AS    53248
#define OFF_ML    53760
#define OFF_AN    54272
#define OFF_SUM   54784
#define OFF_BIAS  55296
#define AGG_SMEM  55552

__global__ __launch_bounds__(256) void agg_k(const float* __restrict__ bias,
                                             float* __restrict__ out) {
    extern __shared__ char sm[];
    __half* sP = (__half*)(sm + OFF_P);
    __half* sV = (__half*)(sm + OFF_V);
    float* sAs = (float*)(sm + OFF_AS);
    float* sMl = (float*)(sm + OFF_ML);
    float* sAn = (float*)(sm + OFF_AN);
    float* sSum = (float*)(sm + OFF_SUM);
    float* sBias = (float*)(sm + OFF_BIAS);

    const int tid = threadIdx.x;
    const int l = tid & 31;
    const int w = tid >> 5;
    const int h  = blockIdx.x;
    const int nt = blockIdx.y;
    const int b  = blockIdx.z;
    const int n0 = nt * 128;

    // ---- preloads
    if (tid < 64) sBias[tid] = bias[h * Uq + tid];
    if (tid < 128) {
        float as = g_as[((size_t)(b * Nq + n0 + tid)) * Hq + h];
        float x = as + g_cm[b * 8 + h];
        float mr = x > 0.f ? x : 0.2f * x;
        sAs[tid] = as;
        sMl[tid] = mr * L2E;
        sSum[tid] = 0.f;
    }

    const uint32_t pBase = smem_u32(sP);
    const uint32_t vBase = smem_u32(sV);

    float acc[8][4];
#pragma unroll
    for (int nf = 0; nf < 8; nf++)
#pragma unroll
        for (int r = 0; r < 4; r++) acc[nf][r] = 0.0f;

    for (int kt = 0; kt < 8; kt++) {
        __syncthreads();      // prev mma done with P/V; preload visible on kt=0
        if (tid < 128)
            sAn[tid] = g_an[((size_t)(b * Nq + kt * 128 + tid)) * Hq + h];
        // V tile: 128 rows x 64 cols fp16
#pragma unroll
        for (int i = 0; i < 4; i++) {
            int s = i * 256 + tid;
            int row = s >> 3, q = s & 7;
            uint4 v = *(const uint4*)(g_feat16 +
                ((size_t)(b * Nq + kt * 128 + row)) * HU + h * Uq + q * 8);
            *(uint4*)&sV[row * VSTRIDE + q * 8] = v;
        }
        // zero P
        uint4 z = make_uint4(0, 0, 0, 0);
#pragma unroll
        for (int i = 0; i < 9; i++) {
            int s = i * 256 + tid;
            if (s < 2176) ((uint4*)sP)[s] = z;
        }
        __syncthreads();
        // scatter this segment's edges
        int seg = ((b * 8 + nt) * 8 + kt);
        int ce = g_ecnt[seg];
        const unsigned short* eb = g_edges + (size_t)seg * ECAP;
        for (int e = tid; e < ce; e += 256) {
            int pk = eb[e];
            int r = pk >> 7, kl = pk & 127;
            float x = sAs[r] + sAn[kl];
            float y = x > 0.f ? x : 0.2f * x;
            float wv = ex2f(fmaf(y, L2E, -sMl[r]));
            sP[r * PSTRIDE + kl] = __float2half_rn(wv);
            atomicAdd(&sSum[r], wv);
        }
        __syncthreads();
        // mma: rows w*16..+16, acc += P x V
#pragma unroll
        for (int kk = 0; kk < 8; kk++) {
            uint32_t a0, a1, a2, a3;
            int arow = w * 16 + (l & 15);
            int acol = kk * 16 + (l >> 4) * 8;
            ldsm_x4(pBase + (arow * PSTRIDE + acol) * 2, a0, a1, a2, a3);
#pragma unroll
            for (int nf = 0; nf < 8; nf++) {
                uint32_t b0, b1;
                int lr = l & 15;
                int brow = kk * 16 + (lr & 7) + (lr >> 3) * 8;
                ldsm_x2t(vBase + (brow * VSTRIDE + nf * 8) * 2, b0, b1);
                mma16816_hf(acc[nf], a0, a1, a2, a3, b0, b1);
            }
        }
    }
    __syncthreads();          // final sSum visible

    // ---- epilogue
    int r1 = w * 16 + (l >> 2);
    int r2 = r1 + 8;
    float i1 = 1.f / sSum[r1];
    float i2 = 1.f / sSum[r2];
#pragma unroll
    for (int nf = 0; nf < 8; nf++) {
        int c = nf * 8 + (l & 3) * 2;
        size_t o1 = ((size_t)(b * Nq + n0 + r1)) * HU + h * Uq + c;
        size_t o2 = ((size_t)(b * Nq + n0 + r2)) * HU + h * Uq + c;
        float2 res1 = __half22float2(*(const __half2*)(g_fres16 + o1));
        float2 res2 = __half22float2(*(const __half2*)(g_fres16 + o2));
        float bx = sBias[c], by = sBias[c + 1];
        float2 v1, v2;
        v1.x = fmaxf(acc[nf][0] * i1 + res1.x + bx, 0.f);
        v1.y = fmaxf(acc[nf][1] * i1 + res1.y + by, 0.f);
        v2.x = fmaxf(acc[nf][2] * i2 + res2.x + bx, 0.f);
        v2.y = fmaxf(acc[nf][3] * i2 + res2.y + by, 0.f);
        *(float2*)(out + o1) = v1;
        *(float2*)(out + o2) = v2;
    }
}

// -------------------------------- launch ---------------------------------
extern "C" void kernel_launch(void* const* d_in, const int* in_sizes, int n_in,
                              void* d_out, int out_size) {
    const float* X    = (const float*)d_in[0];
    const float* A    = (const float*)d_in[1];
    const float* Wk   = (const float*)d_in[2];
    const float* Wr   = (const float*)d_in[3];
    const float* aks  = (const float*)d_in[4];
    const float* akn  = (const float*)d_in[5];
    const float* bias = (const float*)d_in[6];
    float* out = (float*)d_out;

    static bool attr_set = false;
    if (!attr_set) {
        cudaFuncSetAttribute(agg_k, cudaFuncAttributeMaxDynamicSharedMemorySize, AGG_SMEM);
        attr_set = true;
    }

    wconv_k<<<768 * 1024 / 256, 256>>>(Wk, Wr);
    zero_k<<<1, 512>>>();
    ebuild_k<<<dim3(8, 8), 512>>>(A);
    gemm_mma_k<<<dim3(8, 64), 256>>>(X, aks, akn);
    colmax_k<<<64, 128>>>();
    agg_k<<<dim3(Hq, 8, Bq), 256, AGG_SMEM>>>(bias, out);
}

// round 10
// speedup vs baseline: 1.9280x; 1.2191x over previous
#include <cuda_runtime.h>
#include <cuda_fp16.h>
#include <cuda_bf16.h>
#include <cstdint>

#define Bq 8
#define Nq 1024
#define Dq 256
#define Hq 8
#define Uq 64
#define HU 512

// -------- scratch (device globals; no allocation in kernel_launch) --------
__device__ __half g_feat16[Bq * Nq * HU];     // features (fp16)
__device__ __half g_fres16[Bq * Nq * HU];     // residual features (fp16)
__device__ float  g_as[Bq * Nq * Hq];
__device__ float  g_an[Bq * Nq * Hq];
__device__ float  g_cm[Bq * Hq];
__device__ __nv_bfloat16 gWb[768 * 1024];     // stacked W: rows [hi, hi, lo]
__device__ __nv_bfloat16 gXb[8192 * 768];     // stacked X: cols [hi, lo, hi]
#define ECAP 2560
__device__ unsigned short g_edges[512 * ECAP];
__device__ int g_ecnt[512];

// ------------------------- helpers ---------------------------------------
__device__ __forceinline__ uint32_t smem_u32(const void* p) {
    uint32_t a;
    asm("{ .reg .u64 t; cvta.to.shared.u64 t, %1; cvt.u32.u64 %0, t; }" : "=r"(a) : "l"(p));
    return a;
}
__device__ __forceinline__ uint32_t pkb2(__nv_bfloat16 a, __nv_bfloat16 b) {
    __nv_bfloat162 p = __halves2bfloat162(a, b);
    return *reinterpret_cast<uint32_t*>(&p);
}
__device__ __forceinline__ void ldsm_x4(uint32_t addr, uint32_t& r0, uint32_t& r1,
                                        uint32_t& r2, uint32_t& r3) {
    asm volatile("ldmatrix.sync.aligned.m8n8.x4.shared.b16 {%0,%1,%2,%3}, [%4];"
                 : "=r"(r0), "=r"(r1), "=r"(r2), "=r"(r3) : "r"(addr));
}
__device__ __forceinline__ void ldsm_x2t(uint32_t addr, uint32_t& r0, uint32_t& r1) {
    asm volatile("ldmatrix.sync.aligned.m8n8.x2.trans.shared.b16 {%0,%1}, [%2];"
                 : "=r"(r0), "=r"(r1) : "r"(addr));
}
__device__ __forceinline__ void mma16816_bf(float* d, uint32_t a0, uint32_t a1,
                                            uint32_t a2, uint32_t a3,
                                            uint32_t b0, uint32_t b1) {
    asm volatile(
        "mma.sync.aligned.m16n8k16.row.col.f32.bf16.bf16.f32 "
        "{%0,%1,%2,%3}, {%4,%5,%6,%7}, {%8,%9}, {%0,%1,%2,%3};"
        : "+f"(d[0]), "+f"(d[1]), "+f"(d[2]), "+f"(d[3])
        : "r"(a0), "r"(a1), "r"(a2), "r"(a3), "r"(b0), "r"(b1));
}
__device__ __forceinline__ void mma16816_hf(float* d, uint32_t a0, uint32_t a1,
                                            uint32_t a2, uint32_t a3,
                                            uint32_t b0, uint32_t b1) {
    asm volatile(
        "mma.sync.aligned.m16n8k16.row.col.f32.f16.f16.f32 "
        "{%0,%1,%2,%3}, {%4,%5,%6,%7}, {%8,%9}, {%0,%1,%2,%3};"
        : "+f"(d[0]), "+f"(d[1]), "+f"(d[2]), "+f"(d[3])
        : "r"(a0), "r"(a1), "r"(a2), "r"(a3), "r"(b0), "r"(b1));
}
__device__ __forceinline__ float ex2f(float x) {
    float r;
    asm("ex2.approx.f32 %0, %1;" : "=f"(r) : "f"(x));
    return r;
}
#define CPA16(dst, src) \
    asm volatile("cp.async.cg.shared.global [%0], [%1], 16;" :: "r"(dst), "l"(src))
#define L2E 1.4426950408889634f

// ------------- Kernel 0: W -> stacked bf16 [768][1024] + zero counters ----
__global__ __launch_bounds__(256) void wconv_k(const float* __restrict__ Wk,
                                               const float* __restrict__ Wr) {
    if (blockIdx.x == 0) {
        g_ecnt[threadIdx.x] = 0;
        g_ecnt[256 + threadIdx.x] = 0;
    }
    int idx = blockIdx.x * 256 + threadIdx.x;
    int kv = idx >> 10;
    int nc = idx & 1023;
    int part = kv >> 8;
    int k = kv & 255;
    const float* W = (nc >> 9) ? Wr : Wk;
    float x = W[(size_t)k * HU + (nc & 511)];
    __nv_bfloat16 hb = __float2bfloat16_rn(x);
    __nv_bfloat16 o = (part == 2) ? __float2bfloat16_rn(x - __bfloat162float(hb)) : hb;
    gWb[idx] = o;
}

// ------------- Kernel 0b: X -> stacked bf16 [8192][768] -------------------
__global__ __launch_bounds__(256) void xconv_k(const float* __restrict__ X) {
    int idx = blockIdx.x * 256 + threadIdx.x;   // 786432 uint4 slots
    int m = idx / 96;
    int c8 = idx - m * 96;
    int c = c8 * 8;
    int part = c >> 8;          // 0:hi 1:lo 2:hi
    int sc = c & 255;
    const float* src = X + (size_t)m * Dq + sc;
    float4 v0 = *(const float4*)(src);
    float4 v1 = *(const float4*)(src + 4);
    float f[8] = {v0.x, v0.y, v0.z, v0.w, v1.x, v1.y, v1.z, v1.w};
    uint32_t p[4];
#pragma unroll
    for (int j = 0; j < 4; j++) {
        __nv_bfloat16 h0 = __float2bfloat16_rn(f[2 * j]);
        __nv_bfloat16 h1 = __float2bfloat16_rn(f[2 * j + 1]);
        if (part == 1) {
            h0 = __float2bfloat16_rn(f[2 * j] - __bfloat162float(h0));
            h1 = __float2bfloat16_rn(f[2 * j + 1] - __bfloat162float(h1));
        }
        p[j] = pkb2(h0, h1);
    }
    *(uint4*)&gXb[(size_t)m * 768 + c] = make_uint4(p[0], p[1], p[2], p[3]);
}

// ------------- Kernel 0c: edge-list build, 512 blocks ---------------------
// grid (rs=8, nt=8, b=8), 512 threads: warp w owns row rs*16+w.
__global__ __launch_bounds__(512) void ebuild_k(const float* __restrict__ A) {
    const int rs = blockIdx.x, nt = blockIdx.y, b = blockIdx.z;
    const int l = threadIdx.x & 31, w = threadIdx.x >> 5;
    const int r = rs * 16 + w;
    const float4* Ar = (const float4*)(A + ((size_t)(b * Nq + nt * 128 + r)) * Nq);
#pragma unroll
    for (int kt = 0; kt < 8; kt++) {
        float4 v = Ar[kt * 32 + l];
        unsigned b0 = __ballot_sync(~0u, v.x > 0.f);
        unsigned b1 = __ballot_sync(~0u, v.y > 0.f);
        unsigned b2 = __ballot_sync(~0u, v.z > 0.f);
        unsigned b3 = __ballot_sync(~0u, v.w > 0.f);
        int t0 = __popc(b0), t1 = __popc(b1), t2 = __popc(b2), t3 = __popc(b3);
        int tot = t0 + t1 + t2 + t3;
        int base = 0;
        int seg = ((b * 8 + nt) * 8 + kt);
        if (l == 0 && tot) base = atomicAdd(&g_ecnt[seg], tot);
        base = __shfl_sync(~0u, base, 0);
        unsigned lm = (1u << l) - 1u;
        unsigned short* eb = g_edges + (size_t)seg * ECAP + base;
        int rr = r << 7;
        if (v.x > 0.f) eb[__popc(b0 & lm)] = (unsigned short)(rr | (l * 4 + 0));
        if (v.y > 0.f) eb[t0 + __popc(b1 & lm)] = (unsigned short)(rr | (l * 4 + 1));
        if (v.z > 0.f) eb[t0 + t1 + __popc(b2 & lm)] = (unsigned short)(rr | (l * 4 + 2));
        if (v.w > 0.f) eb[t0 + t1 + t2 + __popc(b3 & lm)] = (unsigned short)(rr | (l * 4 + 3));
    }
}

// --- Kernel 1: cp.async double-buffered bf16 GEMM + logits ----------------
// grid (8 n-blocks, 64 m-blocks), 256 threads. Dynamic smem 76800B.
#define ASTRIDE 72
#define BSTRIDE 136
#define ABUF 18432
#define BBUF 17408
#define G_OFF_B  36864
#define G_OFF_PART 71680
#define G_OFF_AK 75776
#define G_OFF_AN 76288
#define GEMM_SMEM 76800
__global__ __launch_bounds__(256) void gemm_mma_k(const float* __restrict__ aks,
                                                  const float* __restrict__ akn) {
    extern __shared__ char sm[];
    const uint32_t smBase = smem_u32(sm);
    const uint32_t aBase = smBase;
    const uint32_t bBase = smBase + G_OFF_B;
    float (*s_part)[128][2] = (float (*)[128][2])(sm + G_OFF_PART);
    float* s_ak = (float*)(sm + G_OFF_AK);
    float* s_an = (float*)(sm + G_OFF_AN);

    const int tid = threadIdx.x;
    const int l   = tid & 31;
    const int wid = tid >> 5;
    const int wm  = wid & 1;
    const int wn  = wid >> 1;
    const int bx  = blockIdx.x;
    const int by  = blockIdx.y;
    const int m0  = by * 128;

    if (bx < 4 && tid < 128) {
        s_ak[tid] = aks[bx * 128 + tid];
        s_an[tid] = akn[bx * 128 + tid];
    }

    float acc[4][4][4];
#pragma unroll
    for (int i = 0; i < 4; i++)
#pragma unroll
        for (int j = 0; j < 4; j++)
#pragma unroll
            for (int r = 0; r < 4; r++) acc[i][j][r] = 0.0f;

    // per-thread load coords
    const int a_row = tid >> 1;                 // with i*128 offset rows
    // A: 1024 slots: row=slot>>3 (0..127), c8=slot&7
    // B: 1024 slots: r=slot>>4 (0..63), c8=slot&15

#define LOAD_CHUNK(ic, buf)                                                     \
    do {                                                                        \
        _Pragma("unroll")                                                       \
        for (int i = 0; i < 4; i++) {                                           \
            int slot = i * 256 + tid;                                           \
            int row = slot >> 3, c8 = slot & 7;                                 \
            const __nv_bfloat16* src =                                          \
                gXb + (size_t)(m0 + row) * 768 + (ic) * 64 + c8 * 8;            \
            CPA16(aBase + (buf) * ABUF + row * 144 + c8 * 16, src);             \
        }                                                                       \
        _Pragma("unroll")                                                       \
        for (int i = 0; i < 4; i++) {                                           \
            int slot = i * 256 + tid;                                           \
            int r = slot >> 4, c8 = slot & 15;                                  \
            const __nv_bfloat16* src =                                          \
                gWb + (size_t)((ic) * 64 + r) * 1024 + bx * 128 + c8 * 8;       \
            CPA16(bBase + (buf) * BBUF + r * 272 + c8 * 16, src);               \
        }                                                                       \
        asm volatile("cp.async.commit_group;" ::: "memory");                    \
    } while (0)

    LOAD_CHUNK(0, 0);

    for (int ic = 0; ic < 12; ic++) {
        const int buf = ic & 1;
        if (ic + 1 < 12) {
            LOAD_CHUNK(ic + 1, buf ^ 1);
            asm volatile("cp.async.wait_group 1;" ::: "memory");
        } else {
            asm volatile("cp.async.wait_group 0;" ::: "memory");
        }
        __syncthreads();
        const uint32_t aB = aBase + buf * ABUF;
        const uint32_t bB = bBase + buf * BBUF;
#pragma unroll
        for (int kk = 0; kk < 4; kk++) {
            uint32_t a[4][4], b[4][2];
#pragma unroll
            for (int mf = 0; mf < 4; mf++) {
                int row = wm * 64 + mf * 16 + (l & 15);
                int col = kk * 16 + (l >> 4) * 8;
                ldsm_x4(aB + row * 144 + col * 2,
                        a[mf][0], a[mf][1], a[mf][2], a[mf][3]);
            }
#pragma unroll
            for (int nf = 0; nf < 4; nf++) {
                int lr = l & 15;
                int row = kk * 16 + (lr & 7) + (lr >> 3) * 8;
                int col = wn * 32 + nf * 8;
                ldsm_x2t(bB + row * 272 + col * 2, b[nf][0], b[nf][1]);
            }
#pragma unroll
            for (int mf = 0; mf < 4; mf++)
#pragma unroll
                for (int nf = 0; nf < 4; nf++)
                    mma16816_bf(acc[mf][nf], a[mf][0], a[mf][1], a[mf][2], a[mf][3],
                                b[nf][0], b[nf][1]);
        }
        __syncthreads();
    }

    // ---------------- epilogue ----------------
#pragma unroll
    for (int mf = 0; mf < 4; mf++) {
        int r_lo = wm * 64 + mf * 16 + (l >> 2);
        int m_lo = m0 + r_lo;
        int m_hi = m_lo + 8;
        float sSl = 0.f, sSh = 0.f, sNl = 0.f, sNh = 0.f;
#pragma unroll
        for (int nf = 0; nf < 4; nf++) {
            int col_l = wn * 32 + nf * 8 + (l & 3) * 2;
            float c0 = acc[mf][nf][0], c1 = acc[mf][nf][1];
            float c2 = acc[mf][nf][2], c3 = acc[mf][nf][3];
            if (bx < 4) {
                int col = bx * 128 + col_l;
                *(__half2*)&g_feat16[(size_t)m_lo * HU + col] = __floats2half2_rn(c0, c1);
                *(__half2*)&g_feat16[(size_t)m_hi * HU + col] = __floats2half2_rn(c2, c3);
                sSl += c0 * s_ak[col_l] + c1 * s_ak[col_l + 1];
                sSh += c2 * s_ak[col_l] + c3 * s_ak[col_l + 1];
                sNl += c0 * s_an[col_l] + c1 * s_an[col_l + 1];
                sNh += c2 * s_an[col_l] + c3 * s_an[col_l + 1];
            } else {
                int col = (bx - 4) * 128 + col_l;
                *(__half2*)&g_fres16[(size_t)m_lo * HU + col] = __floats2half2_rn(c0, c1);
                *(__half2*)&g_fres16[(size_t)m_hi * HU + col] = __floats2half2_rn(c2, c3);
            }
        }
        if (bx < 4) {
#pragma unroll
            for (int o = 1; o <= 2; o <<= 1) {
                sSl += __shfl_xor_sync(0xffffffffu, sSl, o);
                sSh += __shfl_xor_sync(0xffffffffu, sSh, o);
                sNl += __shfl_xor_sync(0xffffffffu, sNl, o);
                sNh += __shfl_xor_sync(0xffffffffu, sNh, o);
            }
            if ((l & 3) == 0) {
                s_part[wn][r_lo][0] = sSl;
                s_part[wn][r_lo][1] = sNl;
                s_part[wn][r_lo + 8][0] = sSh;
                s_part[wn][r_lo + 8][1] = sNh;
            }
        }
    }
    __syncthreads();
    if (bx < 4) {
        int row = tid >> 1;
        int sn = tid & 1;
        float v0 = s_part[0][row][sn] + s_part[1][row][sn];
        float v1 = s_part[2][row][sn] + s_part[3][row][sn];
        int m = m0 + row;
        float* dst = sn ? g_an : g_as;
        dst[(size_t)m * Hq + bx * 2] = v0;
        dst[(size_t)m * Hq + bx * 2 + 1] = v1;
    }
}

// --------- Kernel 2: colmax of an per (b,h), coalesced ---------------------
__global__ __launch_bounds__(256) void colmax_k() {
    int b = blockIdx.x;
    int tid = threadIdx.x, l = tid & 31, w = tid >> 5;
    __shared__ float red[8][8];
    float m[4] = {-1e30f, -1e30f, -1e30f, -1e30f};
    const float4* an4 = (const float4*)(g_an + (size_t)b * Nq * Hq);
    for (int s = tid; s < 2048; s += 256) {     // parity of s == tid&1
        float4 v = an4[s];
        m[0] = fmaxf(m[0], v.x); m[1] = fmaxf(m[1], v.y);
        m[2] = fmaxf(m[2], v.z); m[3] = fmaxf(m[3], v.w);
    }
#pragma unroll
    for (int o = 2; o <= 16; o <<= 1)
#pragma unroll
        for (int j = 0; j < 4; j++) m[j] = fmaxf(m[j], __shfl_xor_sync(~0u, m[j], o));
    if (l < 2)
#pragma unroll
        for (int j = 0; j < 4; j++) red[w][(l & 1) * 4 + j] = m[j];
    __syncthreads();
    if (tid < 8) {
        float mm = red[0][tid];
#pragma unroll
        for (int ww = 1; ww < 8; ww++) mm = fmaxf(mm, red[ww][tid]);
        g_cm[b * 8 + tid] = mm;
    }
}

// --------- Kernel 3: sparse-scatter flash aggregation (1 head / block) ----
#define PSTRIDE 136
#define VSTRIDE 72
#define OFF_P     0
#define OFF_V     34816
#define OFF_AS    53248
#define OFF_ML    53760
#define OFF_AN    54272
#define OFF_SUM   54784
#define OFF_BIAS  55296
#define AGG_SMEM  55552

__global__ __launch_bounds__(256) void agg_k(const float* __restrict__ bias,
                                             float* __restrict__ out) {
    extern __shared__ char sm[];
    __half* sP = (__half*)(sm + OFF_P);
    __half* sV = (__half*)(sm + OFF_V);
    float* sAs = (float*)(sm + OFF_AS);
    float* sMl = (float*)(sm + OFF_ML);
    float* sAn = (float*)(sm + OFF_AN);
    float* sSum = (float*)(sm + OFF_SUM);
    float* sBias = (float*)(sm + OFF_BIAS);

    const int tid = threadIdx.x;
    const int l = tid & 31;
    const int w = tid >> 5;
    const int h  = blockIdx.x;
    const int nt = blockIdx.y;
    const int b  = blockIdx.z;
    const int n0 = nt * 128;

    if (tid < 64) sBias[tid] = bias[h * Uq + tid];
    if (tid < 128) {
        float as = g_as[((size_t)(b * Nq + n0 + tid)) * Hq + h];
        float x = as + g_cm[b * 8 + h];
        float mr = x > 0.f ? x : 0.2f * x;
        sAs[tid] = as;
        sMl[tid] = mr * L2E;
        sSum[tid] = 0.f;
    }

    const uint32_t pBase = smem_u32(sP);
    const uint32_t vBase = smem_u32(sV);

    float acc[8][4];
#pragma unroll
    for (int nf = 0; nf < 8; nf++)
#pragma unroll
        for (int r = 0; r < 4; r++) acc[nf][r] = 0.0f;

    for (int kt = 0; kt < 8; kt++) {
        __syncthreads();
        if (tid < 128)
            sAn[tid] = g_an[((size_t)(b * Nq + kt * 128 + tid)) * Hq + h];
#pragma unroll
        for (int i = 0; i < 4; i++) {
            int s = i * 256 + tid;
            int row = s >> 3, q = s & 7;
            uint4 v = *(const uint4*)(g_feat16 +
                ((size_t)(b * Nq + kt * 128 + row)) * HU + h * Uq + q * 8);
            *(uint4*)&sV[row * VSTRIDE + q * 8] = v;
        }
        uint4 z = make_uint4(0, 0, 0, 0);
#pragma unroll
        for (int i = 0; i < 9; i++) {
            int s = i * 256 + tid;
            if (s < 2176) ((uint4*)sP)[s] = z;
        }
        __syncthreads();
        int seg = ((b * 8 + nt) * 8 + kt);
        int ce = g_ecnt[seg];
        const unsigned short* eb = g_edges + (size_t)seg * ECAP;
        for (int e = tid; e < ce; e += 256) {
            int pk = eb[e];
            int r = pk >> 7, kl = pk & 127;
            float x = sAs[r] + sAn[kl];
            float y = x > 0.f ? x : 0.2f * x;
            float wv = ex2f(fmaf(y, L2E, -sMl[r]));
            sP[r * PSTRIDE + kl] = __float2half_rn(wv);
            atomicAdd(&sSum[r], wv);
        }
        __syncthreads();
#pragma unroll
        for (int kk = 0; kk < 8; kk++) {
            uint32_t a0, a1, a2, a3;
            int arow = w * 16 + (l & 15);
            int acol = kk * 16 + (l >> 4) * 8;
            ldsm_x4(pBase + (arow * PSTRIDE + acol) * 2, a0, a1, a2, a3);
#pragma unroll
            for (int nf = 0; nf < 8; nf++) {
                uint32_t b0, b1;
                int lr = l & 15;
                int brow = kk * 16 + (lr & 7) + (lr >> 3) * 8;
                ldsm_x2t(vBase + (brow * VSTRIDE + nf * 8) * 2, b0, b1);
                mma16816_hf(acc[nf], a0, a1, a2, a3, b0, b1);
            }
        }
    }
    __syncthreads();

    int r1 = w * 16 + (l >> 2);
    int r2 = r1 + 8;
    float i1 = 1.f / sSum[r1];
    float i2 = 1.f / sSum[r2];
#pragma unroll
    for (int nf = 0; nf < 8; nf++) {
        int c = nf * 8 + (l & 3) * 2;
        size_t o1 = ((size_t)(b * Nq + n0 + r1)) * HU + h * Uq + c;
        size_t o2 = ((size_t)(b * Nq + n0 + r2)) * HU + h * Uq + c;
        float2 res1 = __half22float2(*(const __half2*)(g_fres16 + o1));
        float2 res2 = __half22float2(*(const __half2*)(g_fres16 + o2));
        float bx = sBias[c], by = sBias[c + 1];
        float2 v1, v2;
        v1.x = fmaxf(acc[nf][0] * i1 + res1.x + bx, 0.f);
        v1.y = fmaxf(acc[nf][1] * i1 + res1.y + by, 0.f);
        v2.x = fmaxf(acc[nf][2] * i2 + res2.x + bx, 0.f);
        v2.y = fmaxf(acc[nf][3] * i2 + res2.y + by, 0.f);
        *(float2*)(out + o1) = v1;
        *(float2*)(out + o2) = v2;
    }
}

// -------------------------------- launch ---------------------------------
extern "C" void kernel_launch(void* const* d_in, const int* in_sizes, int n_in,
                              void* d_out, int out_size) {
    const float* X    = (const float*)d_in[0];
    const float* A    = (const float*)d_in[1];
    const float* Wk   = (const float*)d_in[2];
    const float* Wr   = (const float*)d_in[3];
    const float* aks  = (const float*)d_in[4];
    const float* akn  = (const float*)d_in[5];
    const float* bias = (const float*)d_in[6];
    float* out = (float*)d_out;

    static bool attr_set = false;
    if (!attr_set) {
        cudaFuncSetAttribute(agg_k, cudaFuncAttributeMaxDynamicSharedMemorySize, AGG_SMEM);
        cudaFuncSetAttribute(gemm_mma_k, cudaFuncAttributeMaxDynamicSharedMemorySize, GEMM_SMEM);
        attr_set = true;
    }

    wconv_k<<<768 * 1024 / 256, 256>>>(Wk, Wr);
    xconv_k<<<8192 * 96 / 256, 256>>>(X);
    ebuild_k<<<dim3(8, 8, 8), 512>>>(A);
    gemm_mma_k<<<dim3(8, 64), 256, GEMM_SMEM>>>(aks, akn);
    colmax_k<<<8, 256>>>();
    agg_k<<<dim3(Hq, 8, Bq), 256, AGG_SMEM>>>(bias, out);
}